// round 15
// baseline (speedup 1.0000x reference)
#include <cuda_runtime.h>
#include <cstdint>

#define S_ROWS 50000
#define P_ROWS 10000
#define EMBED_DIM 64
#define T 256
#define BUCKET 448          // per-col capacity; counts ~ Bin(3.2M,1e-4): 320 +/- 18

#define GRID 888            // 148 SMs x 6 blocks (launch_bounds 256,6)
#define SCHUNK4 160         // int4 per scatter chunk = 640 edges (R11 best)
#define ZCHUNK  3200        // float4 per zero chunk

// fixed-capacity by-col buckets, one set per edge list
__device__ int2 g_ent_a[P_ROWS * BUCKET];    // (row, val_bits)
__device__ int2 g_ent_ia[P_ROWS * BUCKET];
__device__ int  g_cur_a[P_ROWS];             // zero at load; reset by reduce_col
__device__ int  g_cur_ia[P_ROWS];

// scheduler state (zero at load; reset by last warp each launch)
__device__ int g_ticket;
__device__ int g_doneA;
__device__ int g_doneB;
__device__ int g_nfin;

__device__ __forceinline__ void red_add_f2(float2* addr, float x, float y) {
    asm volatile("red.global.add.v2.f32 [%0], {%1, %2};"
                 :: "l"(addr), "f"(x), "f"(y) : "memory");
}

// ---- work-unit bodies ----

// R11 body with ONE change: all 4 atomics issued before the 4 dependent
// stores, so 4 independent ATOMG return-chains are in flight per lane.
__device__ __forceinline__ void scatter_chunk(const int4* __restrict__ rows4,
                                              const int4* __restrict__ cols4,
                                              const float4* __restrict__ vals4,
                                              int2* __restrict__ ent,
                                              int* __restrict__ cur,
                                              int chunk, int n4, int lane) {
    int base = chunk * SCHUNK4 + lane;
    #pragma unroll
    for (int k = 0; k < SCHUNK4 / 32; k++) {
        int i = base + k * 32;
        if (i < n4) {
            int4 r = __ldcs(&rows4[i]);
            int4 c = __ldcs(&cols4[i]);
            float4 v = __ldcs(&vals4[i]);
            int p0 = atomicAdd(&cur[c.x], 1);
            int p1 = atomicAdd(&cur[c.y], 1);
            int p2 = atomicAdd(&cur[c.z], 1);
            int p3 = atomicAdd(&cur[c.w], 1);
            ent[c.x * BUCKET + p0] = make_int2(r.x, __float_as_int(v.x));
            ent[c.y * BUCKET + p1] = make_int2(r.y, __float_as_int(v.y));
            ent[c.z * BUCKET + p2] = make_int2(r.z, __float_as_int(v.z));
            ent[c.w * BUCKET + p3] = make_int2(r.w, __float_as_int(v.w));
        }
    }
}

__device__ __forceinline__ void zero_chunk(float4* __restrict__ dst, int n_f4,
                                           int chunk, int lane) {
    int base = chunk * ZCHUNK + lane;
    #pragma unroll 4
    for (int k = 0; k < ZCHUNK / 32; k++) {
        int i = base + k * 32;
        if (i < n_f4) dst[i] = make_float4(0.f, 0.f, 0.f, 0.f);
    }
}

// fused dual-direction reduce for one col:
//   out_p[col] accumulated in registers (gather s_emb[row]),
//   out_s[row] updated via RED with v * p_emb[col].
// Resets the bucket cursor (graph-replay clean).
__device__ __forceinline__ void reduce_col(int col, int lane,
                                           const int2* __restrict__ ent,
                                           int* __restrict__ cur,
                                           const float2* __restrict__ s_emb,
                                           const float2* __restrict__ p_emb,
                                           float2* __restrict__ out_s,
                                           float2* __restrict__ out_p) {
    int cnt = cur[col];                 // warp-uniform
    int start = col * BUCKET;
    int end   = start + cnt;

    float2 pv = __ldg(&p_emb[(unsigned)col * 32 + lane]);
    float2 acc = make_float2(0.f, 0.f);

    int e = start;
    for (; e + 8 <= end; e += 8) {
        int2 pk[8];
        #pragma unroll
        for (int j = 0; j < 8; j++) pk[j] = __ldcs(&ent[e + j]);   // warp-uniform
        float2 sv[8];
        #pragma unroll
        for (int j = 0; j < 8; j++)
            sv[j] = __ldg(&s_emb[(unsigned)pk[j].x * 32 + lane]);
        #pragma unroll
        for (int j = 0; j < 8; j++) {
            float v = __int_as_float(pk[j].y);
            acc.x = fmaf(v, sv[j].x, acc.x);
            acc.y = fmaf(v, sv[j].y, acc.y);
            red_add_f2(&out_s[(unsigned)pk[j].x * 32 + lane], v * pv.x, v * pv.y);
        }
    }
    for (; e < end; e++) {
        int2 pk = __ldcs(&ent[e]);
        float v = __int_as_float(pk.y);
        float2 sv = __ldg(&s_emb[(unsigned)pk.x * 32 + lane]);
        acc.x = fmaf(v, sv.x, acc.x);
        acc.y = fmaf(v, sv.y, acc.y);
        red_add_f2(&out_s[(unsigned)pk.x * 32 + lane], v * pv.x, v * pv.y);
    }

    out_p[(unsigned)col * 32 + lane] = acc;
    if (lane == 0) cur[col] = 0;        // reset for next graph replay
}

__device__ __forceinline__ void mark_done(int* ctr, int lane) {
    __threadfence();
    __syncwarp();
    if (lane == 0) atomicAdd(ctr, 1);
}

__device__ __forceinline__ void wait_done(int* ctr, int target, bool& ok, int lane) {
    if (!ok) {
        if (lane == 0)
            while (atomicAdd(ctr, 0) < target) __nanosleep(128);
        __syncwarp();
        __threadfence();
        ok = true;
    }
}

// ---- the mega-kernel ----
// Ticket order: scatA | zeroA | scatB | zeroB | reduceA cols | reduceB cols.
// Reduce tickets spin-wait on their list's done-counter. Deadlock-free: a warp
// holding a reduce ticket implies all build tickets were already claimed by
// running warps.
__global__ __launch_bounds__(T, 6)
void mega_kernel(const int4* __restrict__ a_rows4,
                 const int4* __restrict__ a_cols4,
                 const float4* __restrict__ a_vals4,
                 const int4* __restrict__ ia_rows4,
                 const int4* __restrict__ ia_cols4,
                 const float4* __restrict__ ia_vals4,
                 const float2* __restrict__ s_emb,
                 const float2* __restrict__ p_emb,
                 float2* __restrict__ out_sc,
                 float2* __restrict__ out_sic,
                 float2* __restrict__ out_pc,
                 float2* __restrict__ out_pic,
                 int n4, int n_zero_f4, int SC, int ZC) {
    const int lane = threadIdx.x & 31;
    const int done_target = SC + ZC;
    const int tA1 = SC;                                // scatter A
    const int tZ1 = tA1 + ZC;                          // zero A
    const int tB1 = tZ1 + SC;                          // scatter B
    const int tY1 = tB1 + ZC;                          // zero B
    const int tRA = tY1;                               // reduce A cols
    const int tRB = tRA + P_ROWS;                      // reduce B cols
    const int tEnd = tRB + P_ROWS;

    bool okA = false, okB = false;

    for (;;) {
        int t;
        if (lane == 0) t = atomicAdd(&g_ticket, 1);
        t = __shfl_sync(0xffffffffu, t, 0);
        if (t >= tEnd) break;

        if (t < tA1) {
            scatter_chunk(a_rows4, a_cols4, a_vals4, g_ent_a, g_cur_a,
                          t, n4, lane);
            mark_done(&g_doneA, lane);
        } else if (t < tZ1) {
            zero_chunk((float4*)out_sc, n_zero_f4, t - tA1, lane);
            mark_done(&g_doneA, lane);
        } else if (t < tB1) {
            scatter_chunk(ia_rows4, ia_cols4, ia_vals4, g_ent_ia, g_cur_ia,
                          t - tZ1, n4, lane);
            mark_done(&g_doneB, lane);
        } else if (t < tY1) {
            zero_chunk((float4*)out_sic, n_zero_f4, t - tB1, lane);
            mark_done(&g_doneB, lane);
        } else if (t < tRB) {
            wait_done(&g_doneA, done_target, okA, lane);
            reduce_col(t - tRA, lane, g_ent_a, g_cur_a, s_emb, p_emb,
                       out_sc, out_pc);
        } else {
            wait_done(&g_doneB, done_target, okB, lane);
            reduce_col(t - tRB, lane, g_ent_ia, g_cur_ia, s_emb, p_emb,
                       out_sic, out_pic);
        }
    }

    // last warp resets scheduler state for the next graph replay
    if (lane == 0) {
        int nw = gridDim.x * (T / 32);
        int f = atomicAdd(&g_nfin, 1);
        if (f == nw - 1) {
            atomicExch(&g_ticket, 0);
            atomicExch(&g_doneA, 0);
            atomicExch(&g_doneB, 0);
            atomicExch(&g_nfin, 0);
        }
    }
}

extern "C" void kernel_launch(void* const* d_in, const int* in_sizes, int n_in,
                              void* d_out, int out_size) {
    const float* student_embeds = (const float*)d_in[0];
    const float* problem_embeds = (const float*)d_in[1];
    const int*   a_rows  = (const int*)d_in[2];
    const int*   a_cols  = (const int*)d_in[3];
    const float* a_vals  = (const float*)d_in[4];
    const int*   ia_rows = (const int*)d_in[5];
    const int*   ia_cols = (const int*)d_in[6];
    const float* ia_vals = (const float*)d_in[7];

    float* out = (float*)d_out;
    const int nnz = in_sizes[2];
    const int n4 = nnz / 4;                          // 800000

    float* out_student_c  = out;
    float* out_student_ic = out + S_ROWS * EMBED_DIM;
    float* out_problem_c  = out + 2 * S_ROWS * EMBED_DIM;
    float* out_problem_ic = out + 2 * S_ROWS * EMBED_DIM + P_ROWS * EMBED_DIM;

    int n_zero_f4 = (S_ROWS * EMBED_DIM) / 4;        // 800000 f4 per student out
    int SC = (n4 + SCHUNK4 - 1) / SCHUNK4;           // 5000
    int ZC = (n_zero_f4 + ZCHUNK - 1) / ZCHUNK;      // 250

    mega_kernel<<<GRID, T>>>((const int4*)a_rows, (const int4*)a_cols,
                             (const float4*)a_vals,
                             (const int4*)ia_rows, (const int4*)ia_cols,
                             (const float4*)ia_vals,
                             (const float2*)student_embeds,
                             (const float2*)problem_embeds,
                             (float2*)out_student_c, (float2*)out_student_ic,
                             (float2*)out_problem_c, (float2*)out_problem_ic,
                             n4, n_zero_f4, SC, ZC);
}

// round 16
// speedup vs baseline: 1.0208x; 1.0208x over previous
#include <cuda_runtime.h>
#include <cstdint>

#define S_ROWS 50000
#define P_ROWS 10000
#define EMBED_DIM 64
#define T 256
#define BUCKET 448          // per-col capacity; counts ~ Bin(3.2M,1e-4): 320 +/- 18

#define GRID 888            // 148 SMs x 6 blocks (launch_bounds 256,6)
#define SCHUNK4 160         // int4 per scatter chunk = 640 edges (R11 best)
#define ZCHUNK  3200        // float4 per zero chunk

// fixed-capacity by-col buckets, one set per edge list
__device__ int2 g_ent_a[P_ROWS * BUCKET];    // (row, val_bits)
__device__ int2 g_ent_ia[P_ROWS * BUCKET];
__device__ int  g_cur_a[P_ROWS];             // zero at load; reset by reduce_col
__device__ int  g_cur_ia[P_ROWS];

// scheduler state (zero at load; reset by last warp each launch)
__device__ int g_ticket;
__device__ int g_doneA;
__device__ int g_doneB;
__device__ int g_nfin;

__device__ __forceinline__ void red_add_f2(float2* addr, float x, float y) {
    asm volatile("red.global.add.v2.f32 [%0], {%1, %2};"
                 :: "l"(addr), "f"(x), "f"(y) : "memory");
}

// ---- work-unit bodies (byte-identical to R11, the measured best) ----

__device__ __forceinline__ void scatter_chunk(const int4* __restrict__ rows4,
                                              const int4* __restrict__ cols4,
                                              const float4* __restrict__ vals4,
                                              int2* __restrict__ ent,
                                              int* __restrict__ cur,
                                              int chunk, int n4, int lane) {
    int base = chunk * SCHUNK4 + lane;
    #pragma unroll
    for (int k = 0; k < SCHUNK4 / 32; k++) {
        int i = base + k * 32;
        if (i < n4) {
            int4 r = __ldcs(&rows4[i]);
            int4 c = __ldcs(&cols4[i]);
            float4 v = __ldcs(&vals4[i]);
            int p0 = atomicAdd(&cur[c.x], 1);
            ent[c.x * BUCKET + p0] = make_int2(r.x, __float_as_int(v.x));
            int p1 = atomicAdd(&cur[c.y], 1);
            ent[c.y * BUCKET + p1] = make_int2(r.y, __float_as_int(v.y));
            int p2 = atomicAdd(&cur[c.z], 1);
            ent[c.z * BUCKET + p2] = make_int2(r.z, __float_as_int(v.z));
            int p3 = atomicAdd(&cur[c.w], 1);
            ent[c.w * BUCKET + p3] = make_int2(r.w, __float_as_int(v.w));
        }
    }
}

__device__ __forceinline__ void zero_chunk(float4* __restrict__ dst, int n_f4,
                                           int chunk, int lane) {
    int base = chunk * ZCHUNK + lane;
    #pragma unroll 4
    for (int k = 0; k < ZCHUNK / 32; k++) {
        int i = base + k * 32;
        if (i < n_f4) dst[i] = make_float4(0.f, 0.f, 0.f, 0.f);
    }
}

// fused dual-direction reduce for one col:
//   out_p[col] accumulated in registers (gather s_emb[row]),
//   out_s[row] updated via RED with v * p_emb[col].
// Resets the bucket cursor (graph-replay clean).
__device__ __forceinline__ void reduce_col(int col, int lane,
                                           const int2* __restrict__ ent,
                                           int* __restrict__ cur,
                                           const float2* __restrict__ s_emb,
                                           const float2* __restrict__ p_emb,
                                           float2* __restrict__ out_s,
                                           float2* __restrict__ out_p) {
    int cnt = cur[col];                 // warp-uniform
    int start = col * BUCKET;
    int end   = start + cnt;

    float2 pv = __ldg(&p_emb[(unsigned)col * 32 + lane]);
    float2 acc = make_float2(0.f, 0.f);

    int e = start;
    for (; e + 8 <= end; e += 8) {
        int2 pk[8];
        #pragma unroll
        for (int j = 0; j < 8; j++) pk[j] = __ldcs(&ent[e + j]);   // warp-uniform
        float2 sv[8];
        #pragma unroll
        for (int j = 0; j < 8; j++)
            sv[j] = __ldg(&s_emb[(unsigned)pk[j].x * 32 + lane]);
        #pragma unroll
        for (int j = 0; j < 8; j++) {
            float v = __int_as_float(pk[j].y);
            acc.x = fmaf(v, sv[j].x, acc.x);
            acc.y = fmaf(v, sv[j].y, acc.y);
            red_add_f2(&out_s[(unsigned)pk[j].x * 32 + lane], v * pv.x, v * pv.y);
        }
    }
    for (; e < end; e++) {
        int2 pk = __ldcs(&ent[e]);
        float v = __int_as_float(pk.y);
        float2 sv = __ldg(&s_emb[(unsigned)pk.x * 32 + lane]);
        acc.x = fmaf(v, sv.x, acc.x);
        acc.y = fmaf(v, sv.y, acc.y);
        red_add_f2(&out_s[(unsigned)pk.x * 32 + lane], v * pv.x, v * pv.y);
    }

    out_p[(unsigned)col * 32 + lane] = acc;
    if (lane == 0) cur[col] = 0;        // reset for next graph replay
}

__device__ __forceinline__ void mark_done(int* ctr, int lane) {
    __threadfence();
    __syncwarp();
    if (lane == 0) atomicAdd(ctr, 1);
}

__device__ __forceinline__ void wait_done(int* ctr, int target, bool& ok, int lane) {
    if (!ok) {
        if (lane == 0)
            while (atomicAdd(ctr, 0) < target) __nanosleep(128);
        __syncwarp();
        __threadfence();
        ok = true;
    }
}

// ---- the mega-kernel ----
// NEW ticket order:
//   scatA | zeroA | [buildB interleaved 1:1 with redA] | remaining redA | redB
// Rationale: doneA (the gate for redA) completes as early as possible because
// the whole machine works on build-A first; build-B's short units are folded
// into redA's LTS-saturated window instead of ahead of it.
__global__ __launch_bounds__(T, 6)
void mega_kernel(const int4* __restrict__ a_rows4,
                 const int4* __restrict__ a_cols4,
                 const float4* __restrict__ a_vals4,
                 const int4* __restrict__ ia_rows4,
                 const int4* __restrict__ ia_cols4,
                 const float4* __restrict__ ia_vals4,
                 const float2* __restrict__ s_emb,
                 const float2* __restrict__ p_emb,
                 float2* __restrict__ out_sc,
                 float2* __restrict__ out_sic,
                 float2* __restrict__ out_pc,
                 float2* __restrict__ out_pic,
                 int n4, int n_zero_f4, int SC, int ZC) {
    const int lane = threadIdx.x & 31;
    const int BB = SC + ZC;                   // build-B unit count
    const int done_target = BB;               // same target for A and B
    const int tA1 = SC;                       // scatter A
    const int tZ1 = tA1 + ZC;                 // zero A
    const int tMix1 = tZ1 + 2 * BB;           // interleaved buildB/redA
    const int tRA1 = tMix1 + (P_ROWS - BB);   // remaining redA cols
    const int tEnd = tRA1 + P_ROWS;           // redB cols

    bool okA = false, okB = false;

    for (;;) {
        int t;
        if (lane == 0) t = atomicAdd(&g_ticket, 1);
        t = __shfl_sync(0xffffffffu, t, 0);
        if (t >= tEnd) break;

        if (t < tA1) {
            scatter_chunk(a_rows4, a_cols4, a_vals4, g_ent_a, g_cur_a,
                          t, n4, lane);
            mark_done(&g_doneA, lane);
        } else if (t < tZ1) {
            zero_chunk((float4*)out_sc, n_zero_f4, t - tA1, lane);
            mark_done(&g_doneA, lane);
        } else if (t < tMix1) {
            int u = t - tZ1;
            if ((u & 1) == 0) {
                // build-B unit u/2
                int b = u >> 1;
                if (b < SC) {
                    scatter_chunk(ia_rows4, ia_cols4, ia_vals4,
                                  g_ent_ia, g_cur_ia, b, n4, lane);
                } else {
                    zero_chunk((float4*)out_sic, n_zero_f4, b - SC, lane);
                }
                mark_done(&g_doneB, lane);
            } else {
                // redA col u/2  (cols 0 .. BB-1)
                wait_done(&g_doneA, done_target, okA, lane);
                reduce_col(u >> 1, lane, g_ent_a, g_cur_a, s_emb, p_emb,
                           out_sc, out_pc);
            }
        } else if (t < tRA1) {
            // remaining redA cols BB .. P_ROWS-1
            wait_done(&g_doneA, done_target, okA, lane);
            reduce_col(BB + (t - tMix1), lane, g_ent_a, g_cur_a, s_emb, p_emb,
                       out_sc, out_pc);
        } else {
            wait_done(&g_doneB, done_target, okB, lane);
            reduce_col(t - tRA1, lane, g_ent_ia, g_cur_ia, s_emb, p_emb,
                       out_sic, out_pic);
        }
    }

    // last warp resets scheduler state for the next graph replay
    if (lane == 0) {
        int nw = gridDim.x * (T / 32);
        int f = atomicAdd(&g_nfin, 1);
        if (f == nw - 1) {
            atomicExch(&g_ticket, 0);
            atomicExch(&g_doneA, 0);
            atomicExch(&g_doneB, 0);
            atomicExch(&g_nfin, 0);
        }
    }
}

extern "C" void kernel_launch(void* const* d_in, const int* in_sizes, int n_in,
                              void* d_out, int out_size) {
    const float* student_embeds = (const float*)d_in[0];
    const float* problem_embeds = (const float*)d_in[1];
    const int*   a_rows  = (const int*)d_in[2];
    const int*   a_cols  = (const int*)d_in[3];
    const float* a_vals  = (const float*)d_in[4];
    const int*   ia_rows = (const int*)d_in[5];
    const int*   ia_cols = (const int*)d_in[6];
    const float* ia_vals = (const float*)d_in[7];

    float* out = (float*)d_out;
    const int nnz = in_sizes[2];
    const int n4 = nnz / 4;                          // 800000

    float* out_student_c  = out;
    float* out_student_ic = out + S_ROWS * EMBED_DIM;
    float* out_problem_c  = out + 2 * S_ROWS * EMBED_DIM;
    float* out_problem_ic = out + 2 * S_ROWS * EMBED_DIM + P_ROWS * EMBED_DIM;

    int n_zero_f4 = (S_ROWS * EMBED_DIM) / 4;        // 800000 f4 per student out
    int SC = (n4 + SCHUNK4 - 1) / SCHUNK4;           // 5000
    int ZC = (n_zero_f4 + ZCHUNK - 1) / ZCHUNK;      // 250

    mega_kernel<<<GRID, T>>>((const int4*)a_rows, (const int4*)a_cols,
                             (const float4*)a_vals,
                             (const int4*)ia_rows, (const int4*)ia_cols,
                             (const float4*)ia_vals,
                             (const float2*)student_embeds,
                             (const float2*)problem_embeds,
                             (float2*)out_student_c, (float2*)out_student_ic,
                             (float2*)out_problem_c, (float2*)out_problem_ic,
                             n4, n_zero_f4, SC, ZC);
}

// round 17
// speedup vs baseline: 1.0712x; 1.0493x over previous
#include <cuda_runtime.h>
#include <cstdint>

#define S_ROWS 50000
#define P_ROWS 10000
#define EMBED_DIM 64
#define T 256
#define BUCKET 448          // per-col capacity; counts ~ Bin(3.2M,1e-4): 320 +/- 18

#define GRID 888            // 148 SMs x 6 blocks (launch_bounds 256,6)
#define SCHUNK4 160         // int4 per scatter chunk = 640 edges (R11 best)
#define ZCHUNK  3200        // float4 per zero chunk

// fixed-capacity by-col buckets, one set per edge list
__device__ int2 g_ent_a[P_ROWS * BUCKET];    // (row, val_bits)
__device__ int2 g_ent_ia[P_ROWS * BUCKET];
__device__ int  g_cur_a[P_ROWS];             // zero at load; reset by reduce_col
__device__ int  g_cur_ia[P_ROWS];

// scheduler state (zero at load; reset by last warp each launch)
__device__ int g_ticket;
__device__ int g_doneA;
__device__ int g_doneB;
__device__ int g_nfin;

__device__ __forceinline__ void red_add_f2(float2* addr, float x, float y) {
    asm volatile("red.global.add.v2.f32 [%0], {%1, %2};"
                 :: "l"(addr), "f"(x), "f"(y) : "memory");
}

// ---- work-unit bodies (R11 measured-best forms) ----

// 4 interleaved atomicAdd;store chains per lane iteration.
__device__ __forceinline__ void scatter_chunk(const int4* __restrict__ rows4,
                                              const int4* __restrict__ cols4,
                                              const float4* __restrict__ vals4,
                                              int2* __restrict__ ent,
                                              int* __restrict__ cur,
                                              int chunk, int n4, int lane) {
    int base = chunk * SCHUNK4 + lane;
    #pragma unroll
    for (int k = 0; k < SCHUNK4 / 32; k++) {
        int i = base + k * 32;
        if (i < n4) {
            int4 r = __ldcs(&rows4[i]);
            int4 c = __ldcs(&cols4[i]);
            float4 v = __ldcs(&vals4[i]);
            int p0 = atomicAdd(&cur[c.x], 1);
            ent[c.x * BUCKET + p0] = make_int2(r.x, __float_as_int(v.x));
            int p1 = atomicAdd(&cur[c.y], 1);
            ent[c.y * BUCKET + p1] = make_int2(r.y, __float_as_int(v.y));
            int p2 = atomicAdd(&cur[c.z], 1);
            ent[c.z * BUCKET + p2] = make_int2(r.z, __float_as_int(v.z));
            int p3 = atomicAdd(&cur[c.w], 1);
            ent[c.w * BUCKET + p3] = make_int2(r.w, __float_as_int(v.w));
        }
    }
}

__device__ __forceinline__ void zero_chunk(float4* __restrict__ dst, int n_f4,
                                           int chunk, int lane) {
    int base = chunk * ZCHUNK + lane;
    #pragma unroll 4
    for (int k = 0; k < ZCHUNK / 32; k++) {
        int i = base + k * 32;
        if (i < n_f4) dst[i] = make_float4(0.f, 0.f, 0.f, 0.f);
    }
}

// fused dual-direction reduce for one col:
//   out_p[col] accumulated in registers (gather s_emb[row]),
//   out_s[row] updated via RED with v * p_emb[col].
// Resets the bucket cursor (graph-replay clean).
__device__ __forceinline__ void reduce_col(int col, int lane,
                                           const int2* __restrict__ ent,
                                           int* __restrict__ cur,
                                           const float2* __restrict__ s_emb,
                                           const float2* __restrict__ p_emb,
                                           float2* __restrict__ out_s,
                                           float2* __restrict__ out_p) {
    int cnt = cur[col];                 // warp-uniform
    int start = col * BUCKET;
    int end   = start + cnt;

    float2 pv = __ldg(&p_emb[(unsigned)col * 32 + lane]);
    float2 acc = make_float2(0.f, 0.f);

    int e = start;
    for (; e + 8 <= end; e += 8) {
        int2 pk[8];
        #pragma unroll
        for (int j = 0; j < 8; j++) pk[j] = __ldcs(&ent[e + j]);   // warp-uniform
        float2 sv[8];
        #pragma unroll
        for (int j = 0; j < 8; j++)
            sv[j] = __ldg(&s_emb[(unsigned)pk[j].x * 32 + lane]);
        #pragma unroll
        for (int j = 0; j < 8; j++) {
            float v = __int_as_float(pk[j].y);
            acc.x = fmaf(v, sv[j].x, acc.x);
            acc.y = fmaf(v, sv[j].y, acc.y);
            red_add_f2(&out_s[(unsigned)pk[j].x * 32 + lane], v * pv.x, v * pv.y);
        }
    }
    for (; e < end; e++) {
        int2 pk = __ldcs(&ent[e]);
        float v = __int_as_float(pk.y);
        float2 sv = __ldg(&s_emb[(unsigned)pk.x * 32 + lane]);
        acc.x = fmaf(v, sv.x, acc.x);
        acc.y = fmaf(v, sv.y, acc.y);
        red_add_f2(&out_s[(unsigned)pk.x * 32 + lane], v * pv.x, v * pv.y);
    }

    out_p[(unsigned)col * 32 + lane] = acc;
    if (lane == 0) cur[col] = 0;        // reset for next graph replay
}

__device__ __forceinline__ void mark_done(int* ctr, int lane) {
    __threadfence();
    __syncwarp();
    if (lane == 0) atomicAdd(ctr, 1);
}

__device__ __forceinline__ void wait_done(int* ctr, int target, bool& ok, int lane) {
    if (!ok) {
        if (lane == 0)
            while (atomicAdd(ctr, 0) < target) __nanosleep(128);
        __syncwarp();
        __threadfence();
        ok = true;
    }
}

// ---- the mega-kernel ----
// Ticket order: scatA | zeroA | scatB | zeroB | reduceA cols | reduceB cols.
// Reduce tickets spin-wait on their list's done-counter. Deadlock-free: a warp
// holding a reduce ticket implies all build tickets were already claimed by
// running warps.
__global__ __launch_bounds__(T, 6)
void mega_kernel(const int4* __restrict__ a_rows4,
                 const int4* __restrict__ a_cols4,
                 const float4* __restrict__ a_vals4,
                 const int4* __restrict__ ia_rows4,
                 const int4* __restrict__ ia_cols4,
                 const float4* __restrict__ ia_vals4,
                 const float2* __restrict__ s_emb,
                 const float2* __restrict__ p_emb,
                 float2* __restrict__ out_sc,
                 float2* __restrict__ out_sic,
                 float2* __restrict__ out_pc,
                 float2* __restrict__ out_pic,
                 int n4, int n_zero_f4, int SC, int ZC) {
    const int lane = threadIdx.x & 31;
    const int done_target = SC + ZC;
    const int tA1 = SC;                                // scatter A
    const int tZ1 = tA1 + ZC;                          // zero A
    const int tB1 = tZ1 + SC;                          // scatter B
    const int tY1 = tB1 + ZC;                          // zero B
    const int tRA = tY1;                               // reduce A cols
    const int tRB = tRA + P_ROWS;                      // reduce B cols
    const int tEnd = tRB + P_ROWS;

    bool okA = false, okB = false;

    for (;;) {
        int t;
        if (lane == 0) t = atomicAdd(&g_ticket, 1);
        t = __shfl_sync(0xffffffffu, t, 0);
        if (t >= tEnd) break;

        if (t < tA1) {
            scatter_chunk(a_rows4, a_cols4, a_vals4, g_ent_a, g_cur_a,
                          t, n4, lane);
            mark_done(&g_doneA, lane);
        } else if (t < tZ1) {
            zero_chunk((float4*)out_sc, n_zero_f4, t - tA1, lane);
            mark_done(&g_doneA, lane);
        } else if (t < tB1) {
            scatter_chunk(ia_rows4, ia_cols4, ia_vals4, g_ent_ia, g_cur_ia,
                          t - tZ1, n4, lane);
            mark_done(&g_doneB, lane);
        } else if (t < tY1) {
            zero_chunk((float4*)out_sic, n_zero_f4, t - tB1, lane);
            mark_done(&g_doneB, lane);
        } else if (t < tRB) {
            wait_done(&g_doneA, done_target, okA, lane);
            reduce_col(t - tRA, lane, g_ent_a, g_cur_a, s_emb, p_emb,
                       out_sc, out_pc);
        } else {
            wait_done(&g_doneB, done_target, okB, lane);
            reduce_col(t - tRB, lane, g_ent_ia, g_cur_ia, s_emb, p_emb,
                       out_sic, out_pic);
        }
    }

    // last warp resets scheduler state for the next graph replay
    if (lane == 0) {
        int nw = gridDim.x * (T / 32);
        int f = atomicAdd(&g_nfin, 1);
        if (f == nw - 1) {
            atomicExch(&g_ticket, 0);
            atomicExch(&g_doneA, 0);
            atomicExch(&g_doneB, 0);
            atomicExch(&g_nfin, 0);
        }
    }
}

extern "C" void kernel_launch(void* const* d_in, const int* in_sizes, int n_in,
                              void* d_out, int out_size) {
    const float* student_embeds = (const float*)d_in[0];
    const float* problem_embeds = (const float*)d_in[1];
    const int*   a_rows  = (const int*)d_in[2];
    const int*   a_cols  = (const int*)d_in[3];
    const float* a_vals  = (const float*)d_in[4];
    const int*   ia_rows = (const int*)d_in[5];
    const int*   ia_cols = (const int*)d_in[6];
    const float* ia_vals = (const float*)d_in[7];

    float* out = (float*)d_out;
    const int nnz = in_sizes[2];
    const int n4 = nnz / 4;                          // 800000

    float* out_student_c  = out;
    float* out_student_ic = out + S_ROWS * EMBED_DIM;
    float* out_problem_c  = out + 2 * S_ROWS * EMBED_DIM;
    float* out_problem_ic = out + 2 * S_ROWS * EMBED_DIM + P_ROWS * EMBED_DIM;

    int n_zero_f4 = (S_ROWS * EMBED_DIM) / 4;        // 800000 f4 per student out
    int SC = (n4 + SCHUNK4 - 1) / SCHUNK4;           // 5000
    int ZC = (n_zero_f4 + ZCHUNK - 1) / ZCHUNK;      // 250

    mega_kernel<<<GRID, T>>>((const int4*)a_rows, (const int4*)a_cols,
                             (const float4*)a_vals,
                             (const int4*)ia_rows, (const int4*)ia_cols,
                             (const float4*)ia_vals,
                             (const float2*)student_embeds,
                             (const float2*)problem_embeds,
                             (float2*)out_student_c, (float2*)out_student_ic,
                             (float2*)out_problem_c, (float2*)out_problem_ic,
                             n4, n_zero_f4, SC, ZC);
}